// round 4
// baseline (speedup 1.0000x reference)
#include <cuda_runtime.h>
#include <cuda_bf16.h>
#include <cstdint>

// ============================================================================
// Problem dims
// ============================================================================
static constexpr int Mtot = 8192;    // B*S
static constexpr int Hdim = 4096;
static constexpr int Idim = 11008;

static constexpr int BM = 128;
static constexpr int BK = 32;                 // bf16 elems per k-chunk (64B rows)
static constexpr int NSTAGE = 4;

static constexpr int MT    = Mtot / BM;       // 64
static constexpr int NT_GU = Idim / 64;       // 172 (BN=64 per output in kernel2)
static constexpr int NT_DN = Hdim / 128;      // 32  (BN=128 in kernel3)
static constexpr int NCH_GU = Hdim / BK;      // 128
static constexpr int NCH_DN = Idim / BK;      // 344

// per-stage smem: kernel2 {Ahi 8K, Alo 8K, Bg 4K, Bu 4K} = 24K; kernel3 {Ahi, Alo, B} = 24K
static constexpr int STG = 24576;
static constexpr int SMEM_BYTES = NSTAGE * STG;   // 98304

// ============================================================================
// Device scratch (__device__ globals; no allocation allowed)
// ============================================================================
__device__ __nv_bfloat16 g_gate_w[(size_t)Idim * Hdim];
__device__ __nv_bfloat16 g_up_w  [(size_t)Idim * Hdim];
__device__ __nv_bfloat16 g_down_w[(size_t)Hdim * Idim];
__device__ __nv_bfloat16 g_xhi   [(size_t)Mtot * Hdim];
__device__ __nv_bfloat16 g_xlo   [(size_t)Mtot * Hdim];
__device__ __nv_bfloat16 g_phi   [(size_t)Mtot * Idim];
__device__ __nv_bfloat16 g_plo   [(size_t)Mtot * Idim];

// ============================================================================
// Baseline-ISA primitives (compute_103-safe: sm_80-era PTX only)
// ============================================================================
__device__ __forceinline__ uint32_t smem_u32(const void* p) {
    uint32_t a;
    asm("{ .reg .u64 t; cvta.to.shared.u64 t, %1; cvt.u32.u64 %0, t; }" : "=r"(a) : "l"(p));
    return a;
}
__device__ __forceinline__ void cpa16(uint32_t s, const void* g) {
    asm volatile("cp.async.cg.shared.global [%0], [%1], 16;" :: "r"(s), "l"(g));
}
#define CP_COMMIT() asm volatile("cp.async.commit_group;" ::: "memory")
#define CP_WAIT(N)  asm volatile("cp.async.wait_group %0;" :: "n"(N) : "memory")

#define LDSM4(r, addr) \
    asm volatile("ldmatrix.sync.aligned.m8n8.x4.shared.b16 {%0,%1,%2,%3}, [%4];" \
        : "=r"((r)[0]), "=r"((r)[1]), "=r"((r)[2]), "=r"((r)[3]) : "r"(addr))

#define MMA16816(d, a, b0, b1) \
    asm volatile("mma.sync.aligned.m16n8k16.row.col.f32.bf16.bf16.f32 " \
        "{%0,%1,%2,%3}, {%4,%5,%6,%7}, {%8,%9}, {%0,%1,%2,%3};" \
        : "+f"((d)[0]), "+f"((d)[1]), "+f"((d)[2]), "+f"((d)[3]) \
        : "r"((a)[0]), "r"((a)[1]), "r"((a)[2]), "r"((a)[3]), "r"(b0), "r"(b1))

// 64B rows, 4x16B chunks, chunk swizzle c ^ ((r>>1)&3): the 8 rows an ldmatrix
// touches land in 8 distinct 16B bank-groups -> conflict-free LDSM and STS.
__device__ __forceinline__ uint32_t swz(uint32_t base, int r, int c) {
    return base + r * 64 + ((c ^ ((r >> 1) & 3)) << 4);
}
__device__ __forceinline__ uint32_t b2u(__nv_bfloat162 v) {
    return *reinterpret_cast<uint32_t*>(&v);
}

// GROUP_M=8 rasterization for L2 reuse
__device__ __forceinline__ void tile_coords(int bid, int nt, int& mt, int& ntile) {
    const int GROUP_M = 8;
    int per_group = GROUP_M * nt;
    int g = bid / per_group;
    int r = bid % per_group;
    int base = g * GROUP_M;
    int gm = MT - base; if (gm > GROUP_M) gm = GROUP_M;
    mt = base + (r % gm);
    ntile = r / gm;
}

// ============================================================================
// Prep kernels
// ============================================================================
__device__ __forceinline__ uint2 cvt4(int4 a) {
    __nv_bfloat162 p0 = __floats2bfloat162_rn((float)a.x, (float)a.y);
    __nv_bfloat162 p1 = __floats2bfloat162_rn((float)a.z, (float)a.w);
    uint2 r; r.x = b2u(p0); r.y = b2u(p1);
    return r;
}
__global__ void cvt_weights(const int* __restrict__ gq, const int* __restrict__ uq,
                            const int* __restrict__ dq) {
    size_t i = (size_t)blockIdx.x * blockDim.x + threadIdx.x;
    size_t n4 = (size_t)Idim * Hdim / 4;
    if (i >= n4) return;
    reinterpret_cast<uint2*>(g_gate_w)[i] = cvt4(reinterpret_cast<const int4*>(gq)[i]);
    reinterpret_cast<uint2*>(g_up_w)[i]   = cvt4(reinterpret_cast<const int4*>(uq)[i]);
    reinterpret_cast<uint2*>(g_down_w)[i] = cvt4(reinterpret_cast<const int4*>(dq)[i]);
}

__global__ void split_x(const float* __restrict__ x) {
    size_t i = (size_t)blockIdx.x * blockDim.x + threadIdx.x;
    size_t n4 = (size_t)Mtot * Hdim / 4;
    if (i >= n4) return;
    float4 v = reinterpret_cast<const float4*>(x)[i];
    __nv_bfloat162 h0 = __floats2bfloat162_rn(v.x, v.y);
    __nv_bfloat162 h1 = __floats2bfloat162_rn(v.z, v.w);
    float2 f0 = __bfloat1622float2(h0), f1 = __bfloat1622float2(h1);
    __nv_bfloat162 l0 = __floats2bfloat162_rn(v.x - f0.x, v.y - f0.y);
    __nv_bfloat162 l1 = __floats2bfloat162_rn(v.z - f1.x, v.w - f1.y);
    reinterpret_cast<uint2*>(g_xhi)[i] = make_uint2(b2u(h0), b2u(h1));
    reinterpret_cast<uint2*>(g_xlo)[i] = make_uint2(b2u(l0), b2u(l1));
}

// ============================================================================
// Kernel 2: fused gate+up GEMM.  p = (x@gw^T * gs) * (x@uw^T * us), stored hi/lo bf16
// CTA: 128(M) x 64(N, both outputs). 8 warps: 4(M) x 2(N); warp = 32x32 per output.
// ============================================================================
__global__ __launch_bounds__(256, 1)
void gemm_gateup(const float* __restrict__ gate_scale, const float* __restrict__ up_scale) {
    extern __shared__ __align__(128) char smem[];
    const uint32_t s0 = smem_u32(smem);
    const int tid = threadIdx.x;
    const int wid = tid >> 5, lane = tid & 31;
    const int rsel = lane & 15, csel = lane >> 4;
    const int wm = (wid & 3) * 32, wn = (wid >> 2) * 32;

    int mt, nt; tile_coords(blockIdx.x, NT_GU, mt, nt);
    const int m0 = mt * BM, n0 = nt * 64;

    const __nv_bfloat16* pAh = g_xhi    + (size_t)m0 * Hdim;
    const __nv_bfloat16* pAl = g_xlo    + (size_t)m0 * Hdim;
    const __nv_bfloat16* pBg = g_gate_w + (size_t)n0 * Hdim;
    const __nv_bfloat16* pBu = g_up_w   + (size_t)n0 * Hdim;

    // per-chunk cp.async loader
    const int lr = tid >> 2, lc = tid & 3;                // 64 rows x 4 chunks per 256 thr
    const uint32_t loffB = (uint32_t)(lr * 64 + ((lc ^ ((lr >> 1) & 3)) << 4));
    const int lr2 = lr + 64;
    const uint32_t loffA2 = (uint32_t)(lr2 * 64 + ((lc ^ ((lr2 >> 1) & 3)) << 4));
    auto load_chunk = [&](int ch, int st) {
        uint32_t sb = s0 + st * STG;
        size_t ga = (size_t)lr * Hdim + ch * BK + lc * 8;
        size_t ga2 = (size_t)lr2 * Hdim + ch * BK + lc * 8;
        cpa16(sb + loffB,          pAh + ga);
        cpa16(sb + loffA2,         pAh + ga2);
        cpa16(sb + 8192 + loffB,   pAl + ga);
        cpa16(sb + 8192 + loffA2,  pAl + ga2);
        cpa16(sb + 16384 + loffB,  pBg + ga);
        cpa16(sb + 20480 + loffB,  pBu + ga);
        CP_COMMIT();
    };

    float cg[2][4][4], cu[2][4][4];
    #pragma unroll
    for (int g = 0; g < 2; ++g)
        #pragma unroll
        for (int n = 0; n < 4; ++n)
            #pragma unroll
            for (int j = 0; j < 4; ++j) { cg[g][n][j] = 0.f; cu[g][n][j] = 0.f; }

    #pragma unroll
    for (int p = 0; p < NSTAGE - 1; ++p) load_chunk(p, p);

    for (int ch = 0; ch < NCH_GU; ++ch) {
        CP_WAIT(NSTAGE - 2);
        __syncthreads();
        const uint32_t sb = s0 + (ch % NSTAGE) * STG;
        #pragma unroll
        for (int s = 0; s < 2; ++s) {
            uint32_t ah[2][4], al[2][4], bg[2][4], bu[2][4];
            #pragma unroll
            for (int g = 0; g < 2; ++g) {
                LDSM4(ah[g], swz(sb,        wm + g * 16 + rsel, 2 * s + csel));
                LDSM4(al[g], swz(sb + 8192, wm + g * 16 + rsel, 2 * s + csel));
            }
            #pragma unroll
            for (int bt = 0; bt < 2; ++bt) {
                LDSM4(bg[bt], swz(sb + 16384, wn + bt * 16 + rsel, 2 * s + csel));
                LDSM4(bu[bt], swz(sb + 20480, wn + bt * 16 + rsel, 2 * s + csel));
            }
            #pragma unroll
            for (int g = 0; g < 2; ++g)
                #pragma unroll
                for (int n = 0; n < 4; ++n) {
                    int bt = n >> 1, sub = n & 1;
                    MMA16816(cg[g][n], ah[g], bg[bt][sub], bg[bt][2 + sub]);
                    MMA16816(cu[g][n], ah[g], bu[bt][sub], bu[bt][2 + sub]);
                }
            #pragma unroll
            for (int g = 0; g < 2; ++g)
                #pragma unroll
                for (int n = 0; n < 4; ++n) {
                    int bt = n >> 1, sub = n & 1;
                    MMA16816(cg[g][n], al[g], bg[bt][sub], bg[bt][2 + sub]);
                    MMA16816(cu[g][n], al[g], bu[bt][sub], bu[bt][2 + sub]);
                }
        }
        __syncthreads();
        int nx = ch + NSTAGE - 1;
        if (nx < NCH_GU) load_chunk(nx, nx % NSTAGE);
    }

    // Epilogue: p = (g*gs)*(u*us) -> split bf16 hi/lo
    #pragma unroll
    for (int n = 0; n < 4; ++n) {
        int cn = n0 + wn + n * 8 + 2 * (lane & 3);
        float gs0 = gate_scale[cn], gs1 = gate_scale[cn + 1];
        float us0 = up_scale[cn],   us1 = up_scale[cn + 1];
        #pragma unroll
        for (int g = 0; g < 2; ++g) {
            int rr = m0 + wm + g * 16 + (lane >> 2);
            float p00 = (cg[g][n][0] * gs0) * (cu[g][n][0] * us0);
            float p01 = (cg[g][n][1] * gs1) * (cu[g][n][1] * us1);
            float p10 = (cg[g][n][2] * gs0) * (cu[g][n][2] * us0);
            float p11 = (cg[g][n][3] * gs1) * (cu[g][n][3] * us1);
            __nv_bfloat162 h0 = __floats2bfloat162_rn(p00, p01);
            __nv_bfloat162 h1 = __floats2bfloat162_rn(p10, p11);
            float2 f0 = __bfloat1622float2(h0), f1 = __bfloat1622float2(h1);
            __nv_bfloat162 l0 = __floats2bfloat162_rn(p00 - f0.x, p01 - f0.y);
            __nv_bfloat162 l1 = __floats2bfloat162_rn(p10 - f1.x, p11 - f1.y);
            size_t o0 = (size_t)rr * Idim + cn, o1 = (size_t)(rr + 8) * Idim + cn;
            *reinterpret_cast<uint32_t*>(&g_phi[o0]) = b2u(h0);
            *reinterpret_cast<uint32_t*>(&g_plo[o0]) = b2u(l0);
            *reinterpret_cast<uint32_t*>(&g_phi[o1]) = b2u(h1);
            *reinterpret_cast<uint32_t*>(&g_plo[o1]) = b2u(l1);
        }
    }
}

// ============================================================================
// Kernel 3: down GEMM.  out = down_scale * (p @ down_w^T)
// CTA: 128(M) x 128(N). 8 warps: 4(M) x 2(N); warp = 32x64.
// ============================================================================
__global__ __launch_bounds__(256, 1)
void gemm_down(const float* __restrict__ down_scale, float* __restrict__ out) {
    extern __shared__ __align__(128) char smem[];
    const uint32_t s0 = smem_u32(smem);
    const int tid = threadIdx.x;
    const int wid = tid >> 5, lane = tid & 31;
    const int rsel = lane & 15, csel = lane >> 4;
    const int wm = (wid & 3) * 32, wn = (wid >> 2) * 64;

    int mt, nt; tile_coords(blockIdx.x, NT_DN, mt, nt);
    const int m0 = mt * BM, n0 = nt * 128;

    const __nv_bfloat16* pAh = g_phi    + (size_t)m0 * Idim;
    const __nv_bfloat16* pAl = g_plo    + (size_t)m0 * Idim;
    const __nv_bfloat16* pB  = g_down_w + (size_t)n0 * Idim;

    const int lr = tid >> 2, lc = tid & 3;
    const uint32_t loff1 = (uint32_t)(lr * 64 + ((lc ^ ((lr >> 1) & 3)) << 4));
    const int lr2 = lr + 64;
    const uint32_t loff2 = (uint32_t)(lr2 * 64 + ((lc ^ ((lr2 >> 1) & 3)) << 4));
    auto load_chunk = [&](int ch, int st) {
        uint32_t sb = s0 + st * STG;
        size_t ga  = (size_t)lr  * Idim + ch * BK + lc * 8;
        size_t ga2 = (size_t)lr2 * Idim + ch * BK + lc * 8;
        cpa16(sb + loff1,          pAh + ga);
        cpa16(sb + loff2,          pAh + ga2);
        cpa16(sb + 8192 + loff1,   pAl + ga);
        cpa16(sb + 8192 + loff2,   pAl + ga2);
        cpa16(sb + 16384 + loff1,  pB + ga);
        cpa16(sb + 16384 + loff2,  pB + ga2);
        CP_COMMIT();
    };

    float cd[2][8][4];
    #pragma unroll
    for (int g = 0; g < 2; ++g)
        #pragma unroll
        for (int n = 0; n < 8; ++n)
            #pragma unroll
            for (int j = 0; j < 4; ++j) cd[g][n][j] = 0.f;

    #pragma unroll
    for (int p = 0; p < NSTAGE - 1; ++p) load_chunk(p, p);

    for (int ch = 0; ch < NCH_DN; ++ch) {
        CP_WAIT(NSTAGE - 2);
        __syncthreads();
        const uint32_t sb = s0 + (ch % NSTAGE) * STG;
        #pragma unroll
        for (int s = 0; s < 2; ++s) {
            uint32_t ah[2][4], al[2][4], bb[4][4];
            #pragma unroll
            for (int g = 0; g < 2; ++g) {
                LDSM4(ah[g], swz(sb,        wm + g * 16 + rsel, 2 * s + csel));
                LDSM4(al[g], swz(sb + 8192, wm + g * 16 + rsel, 2 * s + csel));
            }
            #pragma unroll
            for (int bt = 0; bt < 4; ++bt)
                LDSM4(bb[bt], swz(sb + 16384, wn + bt * 16 + rsel, 2 * s + csel));
            #pragma unroll
            for (int g = 0; g < 2; ++g)
                #pragma unroll
                for (int n = 0; n < 8; ++n) {
                    int bt = n >> 1, sub = n & 1;
                    MMA16816(cd[g][n], ah[g], bb[bt][sub], bb[bt][2 + sub]);
                }
            #pragma unroll
            for (int g = 0; g < 2; ++g)
                #pragma unroll
                for (int n = 0; n < 8; ++n) {
                    int bt = n >> 1, sub = n & 1;
                    MMA16816(cd[g][n], al[g], bb[bt][sub], bb[bt][2 + sub]);
                }
        }
        __syncthreads();
        int nx = ch + NSTAGE - 1;
        if (nx < NCH_DN) load_chunk(nx, nx % NSTAGE);
    }

    #pragma unroll
    for (int n = 0; n < 8; ++n) {
        int cn = n0 + wn + n * 8 + 2 * (lane & 3);
        float ds0 = down_scale[cn], ds1 = down_scale[cn + 1];
        #pragma unroll
        for (int g = 0; g < 2; ++g) {
            int rr = m0 + wm + g * 16 + (lane >> 2);
            float2 v0 = make_float2(cd[g][n][0] * ds0, cd[g][n][1] * ds1);
            float2 v1 = make_float2(cd[g][n][2] * ds0, cd[g][n][3] * ds1);
            *reinterpret_cast<float2*>(&out[(size_t)rr * Hdim + cn]) = v0;
            *reinterpret_cast<float2*>(&out[(size_t)(rr + 8) * Hdim + cn]) = v1;
        }
    }
}

// ============================================================================
// Launch
// ============================================================================
extern "C" void kernel_launch(void* const* d_in, const int* in_sizes, int n_in,
                              void* d_out, int out_size) {
    (void)in_sizes; (void)n_in; (void)out_size;
    const float* x          = (const float*)d_in[0];
    const int*   gate_wq    = (const int*)  d_in[1];
    const float* gate_scale = (const float*)d_in[2];
    const int*   up_wq      = (const int*)  d_in[3];
    const float* up_scale   = (const float*)d_in[4];
    const int*   down_wq    = (const int*)  d_in[5];
    const float* down_scale = (const float*)d_in[6];
    float* out = (float*)d_out;

    cudaFuncSetAttribute(gemm_gateup, cudaFuncAttributeMaxDynamicSharedMemorySize, SMEM_BYTES);
    cudaFuncSetAttribute(gemm_down,   cudaFuncAttributeMaxDynamicSharedMemorySize, SMEM_BYTES);

    size_t nw4 = (size_t)Idim * Hdim / 4;
    cvt_weights<<<(unsigned)((nw4 + 255) / 256), 256>>>(gate_wq, up_wq, down_wq);
    size_t nx4 = (size_t)Mtot * Hdim / 4;
    split_x<<<(unsigned)((nx4 + 255) / 256), 256>>>(x);

    gemm_gateup<<<MT * NT_GU, 256, SMEM_BYTES>>>(gate_scale, up_scale);
    gemm_down<<<MT * NT_DN, 256, SMEM_BYTES>>>(down_scale, out);
}